// round 12
// baseline (speedup 1.0000x reference)
#include <cuda_runtime.h>
#include <cstdint>

#define D      1024
#define BS     80
#define STEPN  5
#define ALPHA  0.01f
#define NBLK   128
#define NTHR   512

#define WSTRD  1028                 // W smem row stride (floats) -> conflict-free
#define WFL    (16 * WSTRD)         // 16448 floats
#define QSTR   1036                 // q smem row stride (floats) -> conflict-free
#define QFL    (40 * QSTR)          // 41440 floats
#define DYN_FL (WFL + QFL)          // 57888 floats = 231552 B
#define STGS   646                  // epilogue staging stride

// ---- global scratch (no device alloc allowed) ----
__device__ __align__(16) float g_d[BS * 8];     // d[n][t], padded to 8
__device__ __align__(16) float g_y[BS * D];
__device__ __align__(16) float g_csum[2][D];
__device__ __align__(16) float g_csq[2][D];
__device__ unsigned g_rdy[2 * 32];              // half ready counters (padded)
__device__ unsigned g_bar1, g_depart;

// ---- packed fp32x2 helpers ----
__device__ __forceinline__ void ffma2(unsigned long long& acc,
                                      unsigned long long a,
                                      unsigned long long b) {
    asm("fma.rn.f32x2 %0, %1, %2, %0;" : "+l"(acc) : "l"(a), "l"(b));
}
__device__ __forceinline__ float2 fold2f(unsigned long long v) {
    float lo, hi;
    asm("mov.b64 {%0, %1}, %2;" : "=f"(lo), "=f"(hi) : "l"(v));
    return make_float2(lo, hi);
}

// ---- mbarrier + bulk-copy helpers ----
__device__ __forceinline__ uint32_t s2u(const void* p) {
    return (uint32_t)__cvta_generic_to_shared(p);
}
__device__ __forceinline__ void mbar_init(uint32_t a, uint32_t cnt) {
    asm volatile("mbarrier.init.shared.b64 [%0], %1;" :: "r"(a), "r"(cnt) : "memory");
}
__device__ __forceinline__ void mbar_expect(uint32_t a, uint32_t bytes) {
    asm volatile("mbarrier.arrive.expect_tx.shared.b64 _, [%0], %1;"
                 :: "r"(a), "r"(bytes) : "memory");
}
__device__ __forceinline__ void bulk_g2s(uint32_t dst, const void* src,
                                         uint32_t bytes, uint32_t mbar) {
    asm volatile("cp.async.bulk.shared::cta.global.mbarrier::complete_tx::bytes "
                 "[%0], [%1], %2, [%3];"
                 :: "r"(dst), "l"(src), "r"(bytes), "r"(mbar) : "memory");
}
__device__ __forceinline__ void mbar_wait(uint32_t a, uint32_t parity) {
    asm volatile(
        "{\n\t"
        ".reg .pred P1;\n\t"
        "WAIT_LOOP_%=:\n\t"
        "mbarrier.try_wait.parity.acquire.cta.shared::cta.b64 P1, [%0], %1, 0x989680;\n\t"
        "@P1 bra.uni WAIT_DONE_%=;\n\t"
        "bra.uni WAIT_LOOP_%=;\n\t"
        "WAIT_DONE_%=:\n\t"
        "}"
        :: "r"(a), "r"(parity) : "memory");
}

// ---- software grid barrier (single counter; single-wave grid) ----
__device__ __forceinline__ void gridbar(unsigned* cnt) {
    __syncthreads();
    if (threadIdx.x == 0) {
        __threadfence();
        atomicAdd(cnt, 1u);
        while (*(volatile unsigned*)cnt < NBLK) { }
        __threadfence();
    }
    __syncthreads();
}

__global__ void __launch_bounds__(NTHR, 1)
fused_kernel(const float* __restrict__ x, const float* __restrict__ W,
             const float* __restrict__ bias, const float* __restrict__ gamma,
             const float* __restrict__ beta, float* __restrict__ out) {
    extern __shared__ __align__(16) float dynsm[];
    float* smW = dynsm;            // [16][WSTRD]
    float* smQ = dynsm + WFL;      // [40][QSTR]

    // phase-A scratch aliases q area (q written only after phase A)
    float* sred = smQ;             // [5][16]
    // epilogue / phase-3 scratch aliases W area (dead after mainloop)
    float* ysbuf = dynsm + 16 * STGS;          // 640
    float* s_r   = dynsm + 16 * STGS + 640;    // 16
    float* s_tot = dynsm + 16 * STGS + 656;    // 1

    __shared__ __align__(8) unsigned long long mbarW;

    const int tid  = threadIdx.x;
    const int bid  = blockIdx.x;
    const int rh   = bid >> 6;
    const int r0   = rh * 40;
    const int ct   = bid & 63;
    const int c0   = ct * 16;
    const int w    = tid >> 5;
    const int lane = tid & 31;

    // ---- issue W tile bulk copy immediately (hidden under phases A/B) ----
    if (tid == 0) {
        mbar_init(s2u(&mbarW), 1);
        asm volatile("fence.proxy.async.shared::cta;" ::: "memory");
        mbar_expect(s2u(&mbarW), 16 * D * 4);
#pragma unroll
        for (int c = 0; c < 16; c++)
            bulk_g2s(s2u(smW + c * WSTRD), W + (c0 + c) * D, D * 4, &mbarW ? s2u(&mbarW) : 0);
    }
    __syncthreads();   // mbar init visible

    // ================= phase A: d scalars (blocks 0..79) ===================
    if (bid < BS) {
        const int n = bid;
        const int b = n & 15;
        const int rb = b * STEPN;
        const int j0 = tid * 2;

        float2 xn2 = *(const float2*)(x + n * D + j0);
        float pd[STEPN];
#pragma unroll
        for (int t = 0; t < STEPN; t++) {
            float2 xs = *(const float2*)(x + (rb + t) * D + j0);
            pd[t] = xs.x * xn2.x + xs.y * xn2.y;
        }
#pragma unroll
        for (int t = 0; t < STEPN; t++) {
#pragma unroll
            for (int o = 16; o > 0; o >>= 1)
                pd[t] += __shfl_down_sync(0xffffffffu, pd[t], o);
            if (lane == 0) sred[t * 16 + w] = pd[t];
        }
        __syncthreads();
        if (tid < STEPN) {
            float v = 0.f;
#pragma unroll
            for (int ww = 0; ww < 16; ww++) v += sred[tid * 16 + ww];
            g_d[n * 8 + tid] = ALPHA * v;
            __threadfence();
        }
        __syncthreads();
        if (tid == 0)
            atomicAdd(&g_rdy[(n >= 40) * 32], 1u);
    }

    // ================= phase B: wait d, local recurrence into smem ========
    if (tid == 0) {
        while (*(volatile unsigned*)&g_rdy[rh * 32] < 40u) { }
    }
    __syncthreads();

    {
        // warp = batch; compute q rows of this half belonging to this batch
        const int b2  = w;
        const int rb2 = b2 * STEPN;
        int nr = 0, rn[3], rs[3];
#pragma unroll
        for (int s2 = 0; s2 < STEPN; s2++) {
            int n2 = s2 * 16 + b2;
            if (n2 >= r0 && n2 < r0 + 40) { rn[nr] = n2; rs[nr] = s2; nr++; }
        }
        const int smax = rs[nr - 1];

        float dv[3][5];
#pragma unroll
        for (int r = 0; r < 3; r++)
#pragma unroll
            for (int t = 0; t < 5; t++)
                dv[r][t] = (r < nr && t <= rs[r]) ? __ldcg(&g_d[rn[r] * 8 + t]) : 0.f;

#pragma unroll
        for (int it = 0; it < 8; it++) {
            const int base = it * 128 + lane * 4;
            float4 xs[5];
#pragma unroll
            for (int t = 0; t < 5; t++)
                if (t <= smax)
                    xs[t] = *(const float4*)(x + (rb2 + t) * D + base);
#pragma unroll
            for (int r = 0; r < 3; r++) {
                if (r < nr) {
                    float4 g = make_float4(0.f, 0.f, 0.f, 0.f);
#pragma unroll
                    for (int t = 0; t < 5; t++) {
                        if (t <= rs[r]) {
                            float d = dv[r][t];
                            float4 xv = xs[t];
                            g.x = g.x * fmaf(-ALPHA * xv.x, xv.x, 1.f) + xv.x * d;
                            g.y = g.y * fmaf(-ALPHA * xv.y, xv.y, 1.f) + xv.y * d;
                            g.z = g.z * fmaf(-ALPHA * xv.z, xv.z, 1.f) + xv.z * d;
                            g.w = g.w * fmaf(-ALPHA * xv.w, xv.w, 1.f) + xv.w * d;
                        }
                    }
                    *(float4*)(smQ + (rn[r] - r0) * QSTR + base) = g;
                }
            }
        }
    }
    __syncthreads();          // q tile resident
    mbar_wait(s2u(&mbarW), 0);

    // ================= GEMM: zero-sync mainloop over resident smem ========
    {
        const int rg = lane >> 2;
        const int cg = lane & 3;
        const int w8 = w * 8;

        int qoff[5][2], wbase[4][2];
#pragma unroll
        for (int m = 0; m < 5; m++)
#pragma unroll
            for (int qd = 0; qd < 2; qd++)
                qoff[m][qd] = (rg * 5 + m) * QSTR + w8 + qd * 4;
#pragma unroll
        for (int cc = 0; cc < 4; cc++)
#pragma unroll
            for (int qd = 0; qd < 2; qd++)
                wbase[cc][qd] = (cc * 4 + cg) * WSTRD + w8 + qd * 4;

        unsigned long long acc[5][4];
#pragma unroll
        for (int m = 0; m < 5; m++)
#pragma unroll
            for (int c = 0; c < 4; c++) acc[m][c] = 0ull;

#pragma unroll
        for (int ch = 0; ch < 8; ch++) {
            const float* bq = smQ + ch * 128;
            const float* bw = smW + ch * 128;
#pragma unroll
            for (int qd = 0; qd < 2; qd++) {
                ulonglong2 qv[5];
#pragma unroll
                for (int m = 0; m < 5; m++)
                    qv[m] = *(const ulonglong2*)(bq + qoff[m][qd]);
#pragma unroll
                for (int cc = 0; cc < 4; cc++) {
                    ulonglong2 wv = *(const ulonglong2*)(bw + wbase[cc][qd]);
#pragma unroll
                    for (int m = 0; m < 5; m++) {
                        ffma2(acc[m][cc], qv[m].x, wv.x);
                        ffma2(acc[m][cc], qv[m].y, wv.y);
                    }
                }
            }
        }

        __syncthreads();   // mainloop done; smem reusable

        // stage folded partials (aliases W area); stride 646 conflict-free
        float* stg = dynsm;
        {
            float2* dst = (float2*)(stg + w * STGS + lane * 20);
#pragma unroll
            for (int m = 0; m < 5; m++) {
                float2 a = fold2f(acc[m][0]);
                float2 b = fold2f(acc[m][1]);
                float2 c = fold2f(acc[m][2]);
                float2 d = fold2f(acc[m][3]);
                dst[m * 2]     = make_float2(a.x + a.y, b.x + b.y);
                dst[m * 2 + 1] = make_float2(c.x + c.y, d.x + d.y);
            }
        }
        __syncthreads();

        // 16-way k-reduce + bias; write y
        for (int idx = tid; idx < 640; idx += NTHR) {
            const int row = idx >> 4, col = idx & 15;
            const int rg2 = row / 5, m = row - rg2 * 5;
            const int cg2 = col & 3, cc = col >> 2;
            const int off = (rg2 * 4 + cg2) * 20 + m * 4 + cc;
            float s = 0.f;
#pragma unroll
            for (int ww = 0; ww < 16; ww++)
                s += stg[ww * STGS + off];
            const float yv = s + bias[c0 + col];
            g_y[(r0 + row) * D + c0 + col] = yv;
            ysbuf[row * 16 + col] = yv;
        }
        __syncthreads();

        // per-column partial stats over this block's 40 rows
        if (tid < 16) {
            float su = 0.f, sq = 0.f;
#pragma unroll
            for (int r = 0; r < 40; r++) {
                float v = ysbuf[r * 16 + tid];
                su += v;
                sq += v * v;
            }
            g_csum[rh][c0 + tid] = su;
            g_csq[rh][c0 + tid]  = sq;
        }
    }

    gridbar(&g_bar1);

    // ================= phase 3: BN + relu + row L2-normalize (512 thr) =====
    {
        const bool act = (bid < BS);
        const int k0 = tid * 2;
        float z0 = 0.f, z1 = 0.f;
        if (act) {
            const int n = bid;
            float2 y2  = *(const float2*)(g_y + n * D + k0);
            float2 s02 = *(const float2*)(&g_csum[0][k0]);
            float2 s12 = *(const float2*)(&g_csum[1][k0]);
            float2 q02 = *(const float2*)(&g_csq[0][k0]);
            float2 q12 = *(const float2*)(&g_csq[1][k0]);
            float2 ga2 = *(const float2*)(gamma + k0);
            float2 be2 = *(const float2*)(beta + k0);

            const float inv = 1.f / (float)BS;
            float mu, var, rstd;
            mu = (s02.x + s12.x) * inv; var = (q02.x + q12.x) * inv - mu * mu;
            rstd = rsqrtf(var + 1e-5f);
            z0 = fmaxf((y2.x - mu) * rstd * ga2.x + be2.x, 0.f);
            mu = (s02.y + s12.y) * inv; var = (q02.y + q12.y) * inv - mu * mu;
            rstd = rsqrtf(var + 1e-5f);
            z1 = fmaxf((y2.y - mu) * rstd * ga2.y + be2.y, 0.f);

            float ss = z0 * z0 + z1 * z1;
#pragma unroll
            for (int o = 16; o > 0; o >>= 1)
                ss += __shfl_down_sync(0xffffffffu, ss, o);
            if (lane == 0) s_r[w] = ss;
        }
        __syncthreads();
        if (act && tid == 0) {
            float t = 0.f;
#pragma unroll
            for (int ww = 0; ww < 16; ww++) t += s_r[ww];
            s_tot[0] = 1.f / fmaxf(sqrtf(t), 1e-12f);
        }
        __syncthreads();
        if (act) {
            float sc = s_tot[0];
            *(float2*)(out + bid * D + k0) = make_float2(z0 * sc, z1 * sc);
        }
    }

    // ---- depart + replay-safe reset of barrier state ----
    if (tid == 0) {
        __threadfence();
        unsigned old = atomicAdd(&g_depart, 1u);
        if (old == NBLK - 1) {
            g_bar1 = 0;
            g_rdy[0] = 0;
            g_rdy[32] = 0;
            __threadfence();
            g_depart = 0;
            __threadfence();
        }
    }
}

extern "C" void kernel_launch(void* const* d_in, const int* in_sizes, int n_in,
                              void* d_out, int out_size) {
    (void)in_sizes; (void)n_in; (void)out_size;
    const float* x     = (const float*)d_in[0];
    const float* W     = (const float*)d_in[1];
    const float* bias  = (const float*)d_in[2];
    const float* gamma = (const float*)d_in[3];
    const float* beta  = (const float*)d_in[4];
    float* out = (float*)d_out;

    static int configured = 0;
    if (!configured) {
        cudaFuncSetAttribute(fused_kernel,
                             cudaFuncAttributeMaxDynamicSharedMemorySize,
                             DYN_FL * (int)sizeof(float));
        configured = 1;
    }
    fused_kernel<<<NBLK, NTHR, DYN_FL * sizeof(float)>>>(x, W, bias, gamma, beta, out);
}

// round 13
// speedup vs baseline: 1.3471x; 1.3471x over previous
#include <cuda_runtime.h>
#include <cstdint>

#define D      1024
#define BS     80
#define NBATCH 16
#define STEPN  5
#define ALPHA  0.01f
#define NBLK   128
#define NTHR   512

#define WSTRD  1028                  // W smem row stride (floats) -> conflict-free
#define WFL    (16 * WSTRD)          // 16448 floats
#define QCH_FL (40 * 128)            // 5120 floats per q chunk stage
#define DYN_FL (WFL + 8 * QCH_FL)    // 57408 floats = 229632 B
#define STGS   646                   // epilogue staging stride (floats)
#define MB_W   8                     // mbar index for W

// ---- global scratch (no device alloc allowed) ----
__device__ __align__(16) float g_qt[8 * 80 * 128];   // chunk-major q, swizzled
__device__ __align__(16) float g_y[BS * D];
__device__ __align__(16) float g_csum[2][D];
__device__ __align__(16) float g_csq[2][D];
__device__ unsigned g_rdy[2 * 32];   // half-row ready counters (padded)
__device__ unsigned g_bar1, g_depart;

// ---- packed fp32x2 helpers ----
__device__ __forceinline__ void ffma2(unsigned long long& acc,
                                      unsigned long long a,
                                      unsigned long long b) {
    asm("fma.rn.f32x2 %0, %1, %2, %0;" : "+l"(acc) : "l"(a), "l"(b));
}
__device__ __forceinline__ float2 fold2f(unsigned long long v) {
    float lo, hi;
    asm("mov.b64 {%0, %1}, %2;" : "=f"(lo), "=f"(hi) : "l"(v));
    return make_float2(lo, hi);
}

// ---- mbarrier + bulk-copy helpers ----
__device__ __forceinline__ uint32_t s2u(const void* p) {
    return (uint32_t)__cvta_generic_to_shared(p);
}
__device__ __forceinline__ void mbar_init(uint32_t a, uint32_t cnt) {
    asm volatile("mbarrier.init.shared.b64 [%0], %1;" :: "r"(a), "r"(cnt) : "memory");
}
__device__ __forceinline__ void mbar_expect(uint32_t a, uint32_t bytes) {
    asm volatile("mbarrier.arrive.expect_tx.shared.b64 _, [%0], %1;"
                 :: "r"(a), "r"(bytes) : "memory");
}
__device__ __forceinline__ void bulk_g2s(uint32_t dst, const void* src,
                                         uint32_t bytes, uint32_t mbar) {
    asm volatile("cp.async.bulk.shared::cta.global.mbarrier::complete_tx::bytes "
                 "[%0], [%1], %2, [%3];"
                 :: "r"(dst), "l"(src), "r"(bytes), "r"(mbar) : "memory");
}
__device__ __forceinline__ void mbar_wait(uint32_t a, uint32_t parity) {
    asm volatile(
        "{\n\t"
        ".reg .pred P1;\n\t"
        "WAIT_LOOP_%=:\n\t"
        "mbarrier.try_wait.parity.acquire.cta.shared::cta.b64 P1, [%0], %1, 0x989680;\n\t"
        "@P1 bra.uni WAIT_DONE_%=;\n\t"
        "bra.uni WAIT_LOOP_%=;\n\t"
        "WAIT_DONE_%=:\n\t"
        "}"
        :: "r"(a), "r"(parity) : "memory");
}

// ---- software grid barrier (single counter; single-wave grid) ----
__device__ __forceinline__ void gridbar(unsigned* cnt) {
    __syncthreads();
    if (threadIdx.x == 0) {
        __threadfence();
        atomicAdd(cnt, 1u);
        while (*(volatile unsigned*)cnt < NBLK) { }
        __threadfence();
    }
    __syncthreads();
}

__global__ void __launch_bounds__(NTHR, 1)
fused_kernel(const float* __restrict__ x, const float* __restrict__ W,
             const float* __restrict__ bias, const float* __restrict__ gamma,
             const float* __restrict__ beta, float* __restrict__ out) {
    extern __shared__ __align__(16) float dynsm[];
    float* smW  = dynsm;            // [16][WSTRD]
    float* qstg = dynsm + WFL;      // 8 x [40][128]

    // phase-1 scratch aliases q stages (copies land only after phase-1 done)
    float* sred = qstg;             // [5][16]
    float* sd   = qstg + 80;        // [5]
    // epilogue / phase-3 scratch aliases W + staging areas (dead post-mainloop)
    float* ysbuf = dynsm + 16 * STGS;        // 640
    float* s_r   = dynsm + 16 * STGS + 640;  // 16
    float* s_tot = dynsm + 16 * STGS + 656;  // 1

    __shared__ __align__(8) unsigned long long mbar[9];  // 0..7 q-full, 8 W-full

    const int tid  = threadIdx.x;
    const int bid  = blockIdx.x;
    const int rh   = bid >> 6;
    const int r0   = rh * 40;
    const int ct   = bid & 63;
    const int c0   = ct * 16;
    const int w    = tid >> 5;
    const int lane = tid & 31;

    // ---- init mbarriers (tid 0); W bulk copy issued by tid 32 (parallel) ----
    if (tid == 0) {
#pragma unroll
        for (int i = 0; i < 9; i++) mbar_init(s2u(&mbar[i]), 1);
        asm volatile("fence.proxy.async.shared::cta;" ::: "memory");
    }
    __syncthreads();   // mbar init visible block-wide
    if (tid == 32) {
        uint32_t mw = s2u(&mbar[MB_W]);
        mbar_expect(mw, 16 * D * 4);
#pragma unroll
        for (int c = 0; c < 16; c++)
            bulk_g2s(s2u(smW + c * WSTRD), W + (c0 + c) * D, D * 4, mw);
    }

    // ---- phase 1: q rows (blocks 0..79), single-pass float2 lanes ----
    if (bid < BS) {
        const int n = bid;
        const int b = n & 15;
        const int s = n >> 4;
        const int rb = b * STEPN;
        const int rot = (n & 7) << 2;
        const int j0 = tid * 2;

        float2 xn2 = *(const float2*)(x + n * D + j0);
        float2 xs[STEPN];
        float pd[STEPN];
#pragma unroll
        for (int t = 0; t < STEPN; t++) {
            xs[t] = *(const float2*)(x + (rb + t) * D + j0);
            pd[t] = xs[t].x * xn2.x + xs[t].y * xn2.y;
        }
#pragma unroll
        for (int t = 0; t < STEPN; t++) {
#pragma unroll
            for (int o = 16; o > 0; o >>= 1)
                pd[t] += __shfl_down_sync(0xffffffffu, pd[t], o);
            if (lane == 0) sred[t * 16 + w] = pd[t];
        }
        __syncthreads();
        if (tid < STEPN) {
            float v = 0.f;
#pragma unroll
            for (int ww = 0; ww < 16; ww++) v += sred[tid * 16 + ww];
            sd[tid] = ALPHA * v;
        }
        __syncthreads();

        // recurrence for the 2 owned columns (x rows already in registers)
        {
            float g0 = 0.f, g1 = 0.f;
#pragma unroll
            for (int t = 0; t < STEPN; t++) {
                if (t <= s) {
                    const float dv = sd[t];
                    const float x0 = xs[t].x, x1 = xs[t].y;
                    g0 = g0 * fmaf(-ALPHA * x0, x0, 1.f) + x0 * dv;
                    g1 = g1 * fmaf(-ALPHA * x1, x1, 1.f) + x1 * dv;
                }
            }
            // chunk-major swizzled store; pair stays consecutive (rot mult of 4)
            const int ch = j0 >> 7;
            const int off = ((j0 & 127) + rot) & 127;
            __stcg((float2*)(g_qt + ch * (80 * 128) + n * 128 + off),
                   make_float2(g0, g1));
        }
        __syncthreads();   // row fully published (all threads stored)
        if (tid == 0) {
            __threadfence();
            atomicAdd(&g_rdy[(n >= 40) * 32], 1u);
        }
    }

    // ================= phase 2: GEMM, all-8-stage pipeline, no mainloop syncs
    {
        const int rg = lane >> 2;
        const int cg = lane & 3;
        const int w8 = w * 8;

        int qoff[5][2], wbase[4][2];
#pragma unroll
        for (int m = 0; m < 5; m++) {
            int row = rg * 5 + m;
            int rot = ((r0 + row) & 7) << 2;
#pragma unroll
            for (int qd = 0; qd < 2; qd++)
                qoff[m][qd] = row * 128 + ((w8 + qd * 4 + rot) & 127);
        }
#pragma unroll
        for (int cc = 0; cc < 4; cc++) {
            int rc = cc * 4 + cg;
#pragma unroll
            for (int qd = 0; qd < 2; qd++)
                wbase[cc][qd] = rc * WSTRD + w8 + qd * 4;
        }

        unsigned long long acc[5][4];
#pragma unroll
        for (int m = 0; m < 5; m++)
#pragma unroll
            for (int c = 0; c < 4; c++) acc[m][c] = 0ull;

        // issuer: wait for this block's 40 rows, then fire all 8 chunk copies
        if (tid == 0) {
            while (*(volatile unsigned*)&g_rdy[rh * 32] < 40u) { }
            __threadfence();
#pragma unroll
            for (int ch = 0; ch < 8; ch++) {
                uint32_t mb = s2u(&mbar[ch]);
                mbar_expect(mb, QCH_FL * 4);
                bulk_g2s(s2u(qstg + ch * QCH_FL),
                         g_qt + ch * (80 * 128) + r0 * 128, QCH_FL * 4, mb);
            }
        }

        mbar_wait(s2u(&mbar[MB_W]), 0);

        for (int ch = 0; ch < 8; ch++) {
            mbar_wait(s2u(&mbar[ch]), 0);

            const float* bq = qstg + ch * QCH_FL;
            const float* bw = smW + ch * 128;
#pragma unroll
            for (int qd = 0; qd < 2; qd++) {
                ulonglong2 qv[5];
#pragma unroll
                for (int m = 0; m < 5; m++)
                    qv[m] = *(const ulonglong2*)(bq + qoff[m][qd]);
#pragma unroll
                for (int cc = 0; cc < 4; cc++) {
                    ulonglong2 wv = *(const ulonglong2*)(bw + wbase[cc][qd]);
#pragma unroll
                    for (int m = 0; m < 5; m++) {
                        ffma2(acc[m][cc], qv[m].x, wv.x);
                        ffma2(acc[m][cc], qv[m].y, wv.y);
                    }
                }
            }
        }

        __syncthreads();   // mainloop done; smem reusable

        // stage folded partials (aliases W area); stride 646 conflict-free
        float* stg = dynsm;
        {
            float2* dst = (float2*)(stg + w * STGS + lane * 20);
#pragma unroll
            for (int m = 0; m < 5; m++) {
                float2 a = fold2f(acc[m][0]);
                float2 b = fold2f(acc[m][1]);
                float2 c = fold2f(acc[m][2]);
                float2 d = fold2f(acc[m][3]);
                dst[m * 2]     = make_float2(a.x + a.y, b.x + b.y);
                dst[m * 2 + 1] = make_float2(c.x + c.y, d.x + d.y);
            }
        }
        __syncthreads();

        // 16-way reduce + bias; write y
        for (int idx = tid; idx < 640; idx += NTHR) {
            const int row = idx >> 4, col = idx & 15;
            const int rg2 = row / 5, m = row - rg2 * 5;
            const int cg2 = col & 3, cc = col >> 2;
            const int off = (rg2 * 4 + cg2) * 20 + m * 4 + cc;
            float s = 0.f;
#pragma unroll
            for (int ww = 0; ww < 16; ww++)
                s += stg[ww * STGS + off];
            const float yv = s + bias[c0 + col];
            g_y[(r0 + row) * D + c0 + col] = yv;
            ysbuf[row * 16 + col] = yv;
        }
        __syncthreads();

        // per-column partial stats over this block's 40 rows
        if (tid < 16) {
            float su = 0.f, sq = 0.f;
#pragma unroll
            for (int r = 0; r < 40; r++) {
                float v = ysbuf[r * 16 + tid];
                su += v;
                sq += v * v;
            }
            g_csum[rh][c0 + tid] = su;
            g_csq[rh][c0 + tid]  = sq;
        }
    }

    gridbar(&g_bar1);

    // ================= phase 3: BN + relu + row L2-normalize (512 thr) =====
    {
        const bool act = (bid < BS);
        const int k0 = tid * 2;
        float z0 = 0.f, z1 = 0.f;
        if (act) {
            const int n = bid;
            float2 y2  = *(const float2*)(g_y + n * D + k0);
            float2 s02 = *(const float2*)(&g_csum[0][k0]);
            float2 s12 = *(const float2*)(&g_csum[1][k0]);
            float2 q02 = *(const float2*)(&g_csq[0][k0]);
            float2 q12 = *(const float2*)(&g_csq[1][k0]);
            float2 ga2 = *(const float2*)(gamma + k0);
            float2 be2 = *(const float2*)(beta + k0);

            const float inv = 1.f / (float)BS;
            float mu, var, rstd;
            mu = (s02.x + s12.x) * inv; var = (q02.x + q12.x) * inv - mu * mu;
            rstd = rsqrtf(var + 1e-5f);
            z0 = fmaxf((y2.x - mu) * rstd * ga2.x + be2.x, 0.f);
            mu = (s02.y + s12.y) * inv; var = (q02.y + q12.y) * inv - mu * mu;
            rstd = rsqrtf(var + 1e-5f);
            z1 = fmaxf((y2.y - mu) * rstd * ga2.y + be2.y, 0.f);

            float ss = z0 * z0 + z1 * z1;
#pragma unroll
            for (int o = 16; o > 0; o >>= 1)
                ss += __shfl_down_sync(0xffffffffu, ss, o);
            if (lane == 0) s_r[w] = ss;
        }
        __syncthreads();
        if (act && tid == 0) {
            float t = 0.f;
#pragma unroll
            for (int ww = 0; ww < 16; ww++) t += s_r[ww];
            s_tot[0] = 1.f / fmaxf(sqrtf(t), 1e-12f);
        }
        __syncthreads();
        if (act) {
            float sc = s_tot[0];
            *(float2*)(out + bid * D + k0) = make_float2(z0 * sc, z1 * sc);
        }
    }

    // ---- depart + replay-safe reset of barrier state ----
    if (tid == 0) {
        __threadfence();
        unsigned old = atomicAdd(&g_depart, 1u);
        if (old == NBLK - 1) {
            g_bar1 = 0;
            g_rdy[0] = 0;
            g_rdy[32] = 0;
            __threadfence();
            g_depart = 0;
            __threadfence();
        }
    }
}

extern "C" void kernel_launch(void* const* d_in, const int* in_sizes, int n_in,
                              void* d_out, int out_size) {
    (void)in_sizes; (void)n_in; (void)out_size;
    const float* x     = (const float*)d_in[0];
    const float* W     = (const float*)d_in[1];
    const float* bias  = (const float*)d_in[2];
    const float* gamma = (const float*)d_in[3];
    const float* beta  = (const float*)d_in[4];
    float* out = (float*)d_out;

    static int configured = 0;
    if (!configured) {
        cudaFuncSetAttribute(fused_kernel,
                             cudaFuncAttributeMaxDynamicSharedMemorySize,
                             DYN_FL * (int)sizeof(float));
        configured = 1;
    }
    fused_kernel<<<NBLK, NTHR, DYN_FL * sizeof(float)>>>(x, W, bias, gamma, beta, out);
}